// round 13
// baseline (speedup 1.0000x reference)
#include <cuda_runtime.h>
#include <cuda_fp16.h>
#include <cstdint>
#include <math.h>

#define HID   7168
#define NEXP  256
#define NTOK  8192
#define NGRP  8
#define EPG   32
#define KGRP  4
#define TOPK  8

#define BM    64
#define BN    128
#define BK    64
#define NCH   (HID / BK)   // 112

#define LO_SCALE 2048.0f
#define LO_INV   (1.0f / 2048.0f)
#define A_PRE    16.0f
#define B_PRE    1024.0f
#define OUT_SCALE (1.0f / (16.0f * 1024.0f))

#define D_EXPERT 4e-6f
#define D_GROUP  2.4e-5f
#define CAP 8192

// stage layout: BK=64 -> 128B rows padded to 144B (conflict-free ldmatrix)
#define LDAB   144
#define AH_OFF 0
#define AL_OFF 9216
#define BH_OFF 18432
#define BL_OFF 36864
#define STAGE  55296
#define NSTG   2
#define SMEM_BYTES (NSTG * STAGE)   // 110592

// Device scratch (allocation is forbidden)
__device__ float  g_logits[NTOK * NEXP];
__device__ __half g_wh[NEXP * HID];
__device__ __half g_wl[NEXP * HID];
__device__ __half g_xh[NTOK * HID];
__device__ __half g_xl[NTOK * HID];
__device__ int    g_fix_count;
__device__ int    g_fix_list[CAP];
__device__ float  g_fix_logits[CAP * NEXP];

// ---------------------------------------------------------------------------
__device__ __forceinline__ uint32_t smem_u32(const void* p) {
    uint32_t a;
    asm("{ .reg .u64 t; cvta.to.shared.u64 t, %1; cvt.u32.u64 %0, t; }" : "=r"(a) : "l"(p));
    return a;
}
#define CP_ASYNC16(dst, src) \
    asm volatile("cp.async.cg.shared.global [%0], [%1], 16;" :: "r"(dst), "l"(src))
#define CP_COMMIT() asm volatile("cp.async.commit_group;" ::: "memory")
#define CP_WAIT0()  asm volatile("cp.async.wait_group 0;" ::: "memory")

#define LDM4(r, addr)                                                         \
    asm volatile("ldmatrix.sync.aligned.m8n8.x4.shared.b16 {%0,%1,%2,%3}, [%4];" \
        : "=r"((r)[0]), "=r"((r)[1]), "=r"((r)[2]), "=r"((r)[3]) : "r"(addr))

#define MMA16816(c, a, b0, b1)                                                \
    asm volatile("mma.sync.aligned.m16n8k16.row.col.f32.f16.f16.f32 "         \
        "{%0,%1,%2,%3}, {%4,%5,%6,%7}, {%8,%9}, {%0,%1,%2,%3};"               \
        : "+f"((c)[0]), "+f"((c)[1]), "+f"((c)[2]), "+f"((c)[3])              \
        : "r"((a)[0]), "r"((a)[1]), "r"((a)[2]), "r"((a)[3]), "r"(b0), "r"(b1))

__device__ __forceinline__ uint32_t pkh(__half a, __half b) {
    __half2 h = __halves2half2(a, b);
    return *reinterpret_cast<uint32_t*>(&h);
}

__device__ __forceinline__ void cvt8(float4 u, float4 v, float pre, uint4& h, uint4& l) {
    const float f[8] = { u.x * pre, u.y * pre, u.z * pre, u.w * pre,
                         v.x * pre, v.y * pre, v.z * pre, v.w * pre };
    __half hi[8], lo[8];
#pragma unroll
    for (int t = 0; t < 8; t++) {
        hi[t] = __float2half_rn(f[t]);
        lo[t] = __float2half_rn((f[t] - __half2float(hi[t])) * LO_SCALE);
    }
    h = make_uint4(pkh(hi[0],hi[1]), pkh(hi[2],hi[3]), pkh(hi[4],hi[5]), pkh(hi[6],hi[7]));
    l = make_uint4(pkh(lo[0],lo[1]), pkh(lo[2],lo[3]), pkh(lo[4],lo[5]), pkh(lo[6],lo[7]));
}

// ---------------------------------------------------------------------------
__global__ void convert_w_kernel(const float* __restrict__ w) {
    if (blockIdx.x == 0 && threadIdx.x == 0) g_fix_count = 0;
    int i = (blockIdx.x * blockDim.x + threadIdx.x) * 8;
    float4 u = *reinterpret_cast<const float4*>(w + i);
    float4 v = *reinterpret_cast<const float4*>(w + i + 4);
    uint4 h, l;
    cvt8(u, v, B_PRE, h, l);
    *reinterpret_cast<uint4*>(&g_wh[i]) = h;
    *reinterpret_cast<uint4*>(&g_wl[i]) = l;
}

__global__ void convert_x_kernel(const float* __restrict__ x) {
    size_t i = ((size_t)blockIdx.x * blockDim.x + threadIdx.x) * 8;
    float4 u = *reinterpret_cast<const float4*>(x + i);
    float4 v = *reinterpret_cast<const float4*>(x + i + 4);
    uint4 h, l;
    cvt8(u, v, A_PRE, h, l);
    *reinterpret_cast<uint4*>(&g_xh[i]) = h;
    *reinterpret_cast<uint4*>(&g_xl[i]) = l;
}

// ---------------------------------------------------------------------------
// stage loader, 256 threads, BK=64 (128B per row-matrix):
//   B: thread t -> row t>>1 of (t&1 ? lo : hi), 8 x 16B
//   A: threads 0-127 -> row t>>1 of (t&1 ? lo : hi), 8 x 16B
// ---------------------------------------------------------------------------
__device__ __forceinline__ void issue_stage(uint32_t sb, int buf, int c,
    const __half* __restrict__ axh, const __half* __restrict__ axl,
    const __half* __restrict__ bwh, const __half* __restrict__ bwl, int tid)
{
    const uint32_t s = sb + (uint32_t)buf * STAGE;
    {
        const int r = tid >> 1, m = tid & 1;
        const __half* src = (m ? bwl : bwh) + (size_t)r * HID + (size_t)c * BK;
        const uint32_t d = s + (m ? BL_OFF : BH_OFF) + (uint32_t)(r * LDAB);
#pragma unroll
        for (int ch = 0; ch < 8; ch++) CP_ASYNC16(d + ch * 16, src + ch * 8);
    }
    if (tid < 2 * BM) {
        const int r = tid >> 1, m = tid & 1;
        const __half* src = (m ? axl : axh) + (size_t)r * HID + (size_t)c * BK;
        const uint32_t d = s + (m ? AL_OFF : AH_OFF) + (uint32_t)(r * LDAB);
#pragma unroll
        for (int ch = 0; ch < 8; ch++) CP_ASYNC16(d + ch * 16, src + ch * 8);
    }
    CP_COMMIT();
}

// ---------------------------------------------------------------------------
// HMMA GEMM: 64 tokens x 128 experts per CTA, 8 warps (2M x 4N, 32x32 each),
// grid (128, 2), 2 CTAs/SM, BK=64 double-buffered.
// ---------------------------------------------------------------------------
__global__ void __launch_bounds__(256, 2)
gemm_hmma_kernel()
{
    extern __shared__ char smem[];
    const uint32_t sb = smem_u32(smem);
    const int tid  = threadIdx.x;
    const int lane = tid & 31;
    const int warp = tid >> 5;
    const int wm   = warp & 1;     // 2 warps along M (32 rows each)
    const int wn   = warp >> 1;    // 4 warps along N (32 cols each)
    const int t0   = blockIdx.x * BM;
    const int e0   = blockIdx.y * BN;

    const __half* axh = g_xh + (size_t)t0 * HID;
    const __half* axl = g_xl + (size_t)t0 * HID;
    const __half* bwh = g_wh + (size_t)e0 * HID;
    const __half* bwl = g_wl + (size_t)e0 * HID;

    const uint32_t a_ld = (uint32_t)((wm * 32 + (lane & 15)) * LDAB) + (lane & 16);
    const uint32_t b_ld = (uint32_t)((wn * 32 + (lane & 7) + ((lane & 16) >> 1)) * LDAB)
                        + (uint32_t)((lane & 8) * 2);

    float c0[2][4][4], c1[2][4][4];
#pragma unroll
    for (int i = 0; i < 2; i++)
#pragma unroll
        for (int j = 0; j < 4; j++)
#pragma unroll
            for (int q = 0; q < 4; q++) { c0[i][j][q] = 0.0f; c1[i][j][q] = 0.0f; }

    issue_stage(sb, 0, 0, axh, axl, bwh, bwl, tid);

    for (int c = 0; c < NCH; c++) {
        CP_WAIT0();          // stage(c) landed (only outstanding group)
        __syncthreads();
        if (c + 1 < NCH) issue_stage(sb, (c + 1) & 1, c + 1, axh, axl, bwh, bwl, tid);

        const uint32_t stg = sb + (uint32_t)(c & 1) * STAGE;
#pragma unroll
        for (int kk = 0; kk < 4; kk++) {
            const uint32_t ko = (uint32_t)(kk * 32);
            uint32_t ah[2][4], al[2][4];
#pragma unroll
            for (int mi = 0; mi < 2; mi++) {
                LDM4(ah[mi], stg + AH_OFF + a_ld + (uint32_t)(mi * 16 * LDAB) + ko);
                LDM4(al[mi], stg + AL_OFF + a_ld + (uint32_t)(mi * 16 * LDAB) + ko);
            }
#pragma unroll
            for (int g = 0; g < 2; g++) {
                uint32_t bh[4], bl[4];
                LDM4(bh, stg + BH_OFF + b_ld + (uint32_t)(g * 16 * LDAB) + ko);
                LDM4(bl, stg + BL_OFF + b_ld + (uint32_t)(g * 16 * LDAB) + ko);
#pragma unroll
                for (int mi = 0; mi < 2; mi++) {
                    MMA16816(c0[mi][g*2+0], ah[mi], bh[0], bh[1]);
                    MMA16816(c0[mi][g*2+1], ah[mi], bh[2], bh[3]);
                    MMA16816(c1[mi][g*2+0], ah[mi], bl[0], bl[1]);
                    MMA16816(c1[mi][g*2+1], ah[mi], bl[2], bl[3]);
                    MMA16816(c1[mi][g*2+0], al[mi], bh[0], bh[1]);
                    MMA16816(c1[mi][g*2+1], al[mi], bh[2], bh[3]);
                }
            }
        }
    }

    const int row0 = t0 + wm * 32 + (lane >> 2);
    const int col0 = e0 + wn * 32 + (lane & 3) * 2;
#pragma unroll
    for (int mi = 0; mi < 2; mi++) {
#pragma unroll
        for (int nj = 0; nj < 4; nj++) {
            float* p0 = g_logits + (size_t)(row0 + mi * 16) * NEXP + col0 + nj * 8;
            float* p1 = g_logits + (size_t)(row0 + mi * 16 + 8) * NEXP + col0 + nj * 8;
            *reinterpret_cast<float2*>(p0) =
                make_float2(fmaf(c1[mi][nj][0], LO_INV, c0[mi][nj][0]) * OUT_SCALE,
                            fmaf(c1[mi][nj][1], LO_INV, c0[mi][nj][1]) * OUT_SCALE);
            *reinterpret_cast<float2*>(p1) =
                make_float2(fmaf(c1[mi][nj][2], LO_INV, c0[mi][nj][2]) * OUT_SCALE,
                            fmaf(c1[mi][nj][3], LO_INV, c0[mi][nj][3]) * OUT_SCALE);
        }
    }
}

// ---------------------------------------------------------------------------
// Routing core (proven): one warp per token; pass1 flags low-margin tokens.
// ---------------------------------------------------------------------------
__device__ __forceinline__ void route_one(const float* __restrict__ lrow,
                                          const float* __restrict__ bias,
                                          int t, int lane, bool pass1,
                                          float* __restrict__ out_idx,
                                          float* __restrict__ out_w)
{
    float cand[NGRP];
    float gsum[NGRP];
#pragma unroll
    for (int j = 0; j < NGRP; j++) {
        const int e = j * 32 + lane;
        const float lg = lrow[e];
        const float s = 1.0f / (1.0f + expf(-lg));
        const float cc = s + __ldg(&bias[e]);
        cand[j] = cc;
        float v = cc;
#pragma unroll
        for (int o = 16; o; o >>= 1) v += __shfl_xor_sync(0xffffffffu, v, o);
        gsum[j] = v;
    }

    unsigned gmask = 0;
    float g4 = 0.0f, g5 = 0.0f;
    {
        float gs[NGRP];
#pragma unroll
        for (int j = 0; j < NGRP; j++) gs[j] = gsum[j];
#pragma unroll
        for (int r = 0; r < KGRP + 1; r++) {
            int bi = 0; float bv = gs[0];
#pragma unroll
            for (int j = 1; j < NGRP; j++) if (gs[j] > bv) { bv = gs[j]; bi = j; }
            if (r < KGRP) { gmask |= 1u << bi; g4 = bv; }
            else          { g5 = bv; }
            gs[bi] = -INFINITY;
        }
    }
    const float margin_g = g4 - g5;

#pragma unroll
    for (int j = 0; j < NGRP; j++)
        if (!((gmask >> j) & 1u)) cand[j] = -INFINITY;

    float wsum = 0.0f, my_w = 0.0f;
    int   my_i = 0;
    float prev = 0.0f, margin_e = INFINITY;
#pragma unroll
    for (int r = 0; r < TOPK + 1; r++) {
        float bv = cand[0];
        int   be = lane;
#pragma unroll
        for (int j = 1; j < NGRP; j++) {
            const int e = j * 32 + lane;
            if (cand[j] > bv) { bv = cand[j]; be = e; }
        }
#pragma unroll
        for (int o = 16; o; o >>= 1) {
            const float ov = __shfl_xor_sync(0xffffffffu, bv, o);
            const int   oe = __shfl_xor_sync(0xffffffffu, be, o);
            if (ov > bv || (ov == bv && oe < be)) { bv = ov; be = oe; }
        }
        if (r > 0) margin_e = fminf(margin_e, prev - bv);
        prev = bv;
        if (r < TOPK) {
            const int jw = be >> 5;
            const int lw = be & 31;
            if (lane == lw) {
#pragma unroll
                for (int j = 0; j < NGRP; j++) if (j == jw) cand[j] = -INFINITY;
            }
            const float wgt = bv - __ldg(&bias[be]);
            wsum += wgt;
            if (lane == r) { my_w = wgt; my_i = be; }
        }
    }

    if (lane < TOPK) {
        out_idx[t * TOPK + lane] = (float)my_i;
        out_w[t * TOPK + lane]   = my_w / (wsum + 1e-20f) * 2.5f;
    }
    if (pass1 && lane == 0 && (margin_e < D_EXPERT || margin_g < D_GROUP)) {
        int idx = atomicAdd(&g_fix_count, 1);
        if (idx < CAP) g_fix_list[idx] = t;
    }
}

__global__ void route_kernel(const float* __restrict__ bias,
                             float* __restrict__ out_idx,
                             float* __restrict__ out_w)
{
    const int warp = threadIdx.x >> 5;
    const int lane = threadIdx.x & 31;
    const int t = blockIdx.x * 8 + warp;
    if (t >= NTOK) return;
    route_one(g_logits + (size_t)t * NEXP, bias, t, lane, true, out_idx, out_w);
}

// ---------------------------------------------------------------------------
// Fixup GEMM (proven R10): unit = (token, 8-expert slice), warp per expert.
// ---------------------------------------------------------------------------
__global__ void fix_gemm_kernel(const float* __restrict__ x,
                                const float* __restrict__ w)
{
    const int cnt = min(g_fix_count, CAP);
    const int units = cnt * 32;
    const int warp = threadIdx.x >> 5;
    const int lane = threadIdx.x & 31;
    for (int u = blockIdx.x; u < units; u += gridDim.x) {
        const int i = u >> 5;
        const int e = (u & 31) * 8 + warp;
        const float4* xr = reinterpret_cast<const float4*>(x + (size_t)g_fix_list[i] * HID);
        const float4* wr = reinterpret_cast<const float4*>(w + (size_t)e * HID);
        float4 s0 = make_float4(0.f,0.f,0.f,0.f), s1 = s0, s2 = s0, s3 = s0;
#pragma unroll
        for (int j = 0; j < 14; j++) {
            const int b = j * 128 + lane;
            const float4 a0 = xr[b],      w0 = wr[b];
            const float4 a1 = xr[b + 32], w1 = wr[b + 32];
            const float4 a2 = xr[b + 64], w2 = wr[b + 64];
            const float4 a3 = xr[b + 96], w3 = wr[b + 96];
            s0.x = fmaf(a0.x, w0.x, s0.x); s0.y = fmaf(a0.y, w0.y, s0.y);
            s0.z = fmaf(a0.z, w0.z, s0.z); s0.w = fmaf(a0.w, w0.w, s0.w);
            s1.x = fmaf(a1.x, w1.x, s1.x); s1.y = fmaf(a1.y, w1.y, s1.y);
            s1.z = fmaf(a1.z, w1.z, s1.z); s1.w = fmaf(a1.w, w1.w, s1.w);
            s2.x = fmaf(a2.x, w2.x, s2.x); s2.y = fmaf(a2.y, w2.y, s2.y);
            s2.z = fmaf(a2.z, w2.z, s2.z); s2.w = fmaf(a2.w, w2.w, s2.w);
            s3.x = fmaf(a3.x, w3.x, s3.x); s3.y = fmaf(a3.y, w3.y, s3.y);
            s3.z = fmaf(a3.z, w3.z, s3.z); s3.w = fmaf(a3.w, w3.w, s3.w);
        }
        float v = (((s0.x + s0.y) + (s0.z + s0.w)) + ((s1.x + s1.y) + (s1.z + s1.w)))
                + (((s2.x + s2.y) + (s2.z + s2.w)) + ((s3.x + s3.y) + (s3.z + s3.w)));
#pragma unroll
        for (int o = 16; o; o >>= 1) v += __shfl_xor_sync(0xffffffffu, v, o);
        if (lane == 0) g_fix_logits[(size_t)i * NEXP + e] = v;
    }
}

__global__ void fix_route_kernel(const float* __restrict__ bias,
                                 float* __restrict__ out_idx,
                                 float* __restrict__ out_w)
{
    const int warp = threadIdx.x >> 5;
    const int lane = threadIdx.x & 31;
    const int i = blockIdx.x * 8 + warp;
    const int cnt = min(g_fix_count, CAP);
    if (i >= cnt) return;
    route_one(g_fix_logits + (size_t)i * NEXP, bias, g_fix_list[i], lane, false,
              out_idx, out_w);
}

// ---------------------------------------------------------------------------
extern "C" void kernel_launch(void* const* d_in, const int* in_sizes, int n_in,
                              void* d_out, int out_size)
{
    const float* x    = (const float*)d_in[0];
    const float* w    = (const float*)d_in[1];
    const float* bias = (const float*)d_in[2];
    float* out = (float*)d_out;
    float* out_w = out + (size_t)NTOK * TOPK;

    cudaFuncSetAttribute(gemm_hmma_kernel, cudaFuncAttributeMaxDynamicSharedMemorySize, SMEM_BYTES);

    convert_w_kernel<<<NEXP * HID / 8 / 256, 256>>>(w);
    convert_x_kernel<<<NTOK * HID / 8 / 256, 256>>>(x);
    gemm_hmma_kernel<<<dim3(128, 2), 256, SMEM_BYTES>>>();
    route_kernel<<<NTOK / 8, 256>>>(bias, out, out_w);
    fix_gemm_kernel<<<2048, 256>>>(x, w);
    fix_route_kernel<<<CAP / 8, 256>>>(bias, out, out_w);
}

// round 14
// speedup vs baseline: 1.2885x; 1.2885x over previous
#include <cuda_runtime.h>
#include <cuda_fp16.h>
#include <cstdint>
#include <math.h>

#define HID   7168
#define NEXP  256
#define NTOK  8192
#define NGRP  8
#define EPG   32
#define KGRP  4
#define TOPK  8

#define BM    64
#define BN    128
#define BK    32
#define NCH   (HID / BK)   // 224

#define LO_SCALE 2048.0f
#define LO_INV   (1.0f / 2048.0f)
#define A_PRE    16.0f
#define B_PRE    1024.0f
#define OUT_SCALE (1.0f / (16.0f * 1024.0f))

#define D_EXPERT 4e-6f
#define D_GROUP  2.4e-5f
#define CAP 8192

// stage layout: rows padded to 80B (conflict-free ldmatrix / 16B-aligned STS)
#define LDAB   80
#define AH_OFF 0
#define AL_OFF 5120
#define BH_OFF 10240
#define BL_OFF 20480
#define STAGE  30720
#define NSTG   3
#define SMEM_BYTES (NSTG * STAGE)   // 92160

// Device scratch (allocation is forbidden)
__device__ float  g_logits[NTOK * NEXP];
__device__ __half g_wh[NEXP * HID];
__device__ __half g_wl[NEXP * HID];
__device__ int    g_fix_count;
__device__ int    g_fix_list[CAP];
__device__ float  g_fix_logits[CAP * NEXP];

// ---------------------------------------------------------------------------
__device__ __forceinline__ uint32_t smem_u32(const void* p) {
    uint32_t a;
    asm("{ .reg .u64 t; cvta.to.shared.u64 t, %1; cvt.u32.u64 %0, t; }" : "=r"(a) : "l"(p));
    return a;
}
#define CP_ASYNC16(dst, src) \
    asm volatile("cp.async.cg.shared.global [%0], [%1], 16;" :: "r"(dst), "l"(src))
#define CP_COMMIT() asm volatile("cp.async.commit_group;" ::: "memory")
#define CP_WAIT0()  asm volatile("cp.async.wait_group 0;" ::: "memory")
#define CP_WAIT1()  asm volatile("cp.async.wait_group 1;" ::: "memory")

#define LDM4(r, addr)                                                         \
    asm volatile("ldmatrix.sync.aligned.m8n8.x4.shared.b16 {%0,%1,%2,%3}, [%4];" \
        : "=r"((r)[0]), "=r"((r)[1]), "=r"((r)[2]), "=r"((r)[3]) : "r"(addr))

#define MMA16816(c, a, b0, b1)                                                \
    asm volatile("mma.sync.aligned.m16n8k16.row.col.f32.f16.f16.f32 "         \
        "{%0,%1,%2,%3}, {%4,%5,%6,%7}, {%8,%9}, {%0,%1,%2,%3};"               \
        : "+f"((c)[0]), "+f"((c)[1]), "+f"((c)[2]), "+f"((c)[3])              \
        : "r"((a)[0]), "r"((a)[1]), "r"((a)[2]), "r"((a)[3]), "r"(b0), "r"(b1))

__device__ __forceinline__ uint32_t pkh(__half a, __half b) {
    __half2 h = __halves2half2(a, b);
    return *reinterpret_cast<uint32_t*>(&h);
}

__device__ __forceinline__ void cvt8(float4 u, float4 v, float pre, uint4& h, uint4& l) {
    const float f[8] = { u.x * pre, u.y * pre, u.z * pre, u.w * pre,
                         v.x * pre, v.y * pre, v.z * pre, v.w * pre };
    __half hi[8], lo[8];
#pragma unroll
    for (int t = 0; t < 8; t++) {
        hi[t] = __float2half_rn(f[t]);
        lo[t] = __float2half_rn((f[t] - __half2float(hi[t])) * LO_SCALE);
    }
    h = make_uint4(pkh(hi[0],hi[1]), pkh(hi[2],hi[3]), pkh(hi[4],hi[5]), pkh(hi[6],hi[7]));
    l = make_uint4(pkh(lo[0],lo[1]), pkh(lo[2],lo[3]), pkh(lo[4],lo[5]), pkh(lo[6],lo[7]));
}

// ---------------------------------------------------------------------------
__global__ void convert_w_kernel(const float* __restrict__ w) {
    if (blockIdx.x == 0 && threadIdx.x == 0) g_fix_count = 0;
    int i = (blockIdx.x * blockDim.x + threadIdx.x) * 8;
    float4 u = *reinterpret_cast<const float4*>(w + i);
    float4 v = *reinterpret_cast<const float4*>(w + i + 4);
    uint4 h, l;
    cvt8(u, v, B_PRE, h, l);
    *reinterpret_cast<uint4*>(&g_wh[i]) = h;
    *reinterpret_cast<uint4*>(&g_wl[i]) = l;
}

// ---------------------------------------------------------------------------
// B-only stage loader (as in R10): thread t -> B row t&127, hi if t<128 else lo
// ---------------------------------------------------------------------------
__device__ __forceinline__ void issue_stage_b(uint32_t sb, int buf, int c,
    const __half* __restrict__ bwh, const __half* __restrict__ bwl, int tid)
{
    const uint32_t s = sb + (uint32_t)buf * STAGE;
    const int row = tid & 127;
    const int sel = tid >> 7;
    const __half* src = (sel ? bwl : bwh) + (size_t)row * HID + (size_t)c * BK;
    const uint32_t d = s + (sel ? BL_OFF : BH_OFF) + (uint32_t)(row * LDAB);
#pragma unroll
    for (int ch = 0; ch < 4; ch++) CP_ASYNC16(d + ch * 16, src + ch * 8);
    CP_COMMIT();
}

// ---------------------------------------------------------------------------
// HMMA GEMM (R10 pipeline) with in-kernel A split:
//   A: LDG fp32 (prefetch 2 chunks ahead) -> cvt hi/lo -> STS one chunk ahead
//   B: cp.async from pre-split g_wh/g_wl, 3-stage rotation (unchanged)
// 64 tokens x 128 experts per CTA, 8 warps 32x32, grid (128,2), 2 CTAs/SM.
// ---------------------------------------------------------------------------
__global__ void __launch_bounds__(256, 2)
gemm_hmma_kernel(const float* __restrict__ x)
{
    extern __shared__ char smem[];
    const uint32_t sb = smem_u32(smem);
    const int tid  = threadIdx.x;
    const int lane = tid & 31;
    const int warp = tid >> 5;
    const int wm   = warp & 1;
    const int wn   = warp >> 1;
    const int t0   = blockIdx.x * BM;
    const int e0   = blockIdx.y * BN;

    // A mapping: thread -> row tid>>2, k-offset (tid&3)*8 (8 fp32 per thread)
    const int arow = tid >> 2;
    const int acol = (tid & 3) * 8;
    const float* ap = x + (size_t)(t0 + arow) * HID + acol;
    const uint32_t a_sts = (uint32_t)(arow * LDAB + (tid & 3) * 16);

    const __half* bwh = g_wh + (size_t)e0 * HID;
    const __half* bwl = g_wl + (size_t)e0 * HID;

    const uint32_t a_ld = (uint32_t)((wm * 32 + (lane & 15)) * LDAB) + (lane & 16);
    const uint32_t b_ld = (uint32_t)((wn * 32 + (lane & 7) + ((lane & 16) >> 1)) * LDAB)
                        + (uint32_t)((lane & 8) * 2);

    float c0[2][4][4], c1[2][4][4];
#pragma unroll
    for (int i = 0; i < 2; i++)
#pragma unroll
        for (int j = 0; j < 4; j++)
#pragma unroll
            for (int q = 0; q < 4; q++) { c0[i][j][q] = 0.0f; c1[i][j][q] = 0.0f; }

    // prologue: A(0) -> smem slot 0; A(1) -> regs; B(0), B(1) in flight
    float4 ar0, ar1;
    {
        ar0 = *reinterpret_cast<const float4*>(ap);
        ar1 = *reinterpret_cast<const float4*>(ap + 4);
        uint4 h, l;
        cvt8(ar0, ar1, A_PRE, h, l);
        *reinterpret_cast<uint4*>(smem + AH_OFF + a_sts) = h;
        *reinterpret_cast<uint4*>(smem + AL_OFF + a_sts) = l;
        ar0 = *reinterpret_cast<const float4*>(ap + BK);
        ar1 = *reinterpret_cast<const float4*>(ap + BK + 4);
    }
    issue_stage_b(sb, 0, 0, bwh, bwl, tid);
    issue_stage_b(sb, 1, 1, bwh, bwl, tid);

    for (int c = 0; c < NCH; c++) {
        if (c + 1 < NCH) CP_WAIT1(); else CP_WAIT0();
        __syncthreads();

        // stage A(c+1) into slot (c+1)%3 (disjoint from MMA(c)'s slot c%3)
        if (c + 1 < NCH) {
            const uint32_t ns = (uint32_t)((c + 1) % NSTG) * STAGE;
            uint4 h, l;
            cvt8(ar0, ar1, A_PRE, h, l);
            *reinterpret_cast<uint4*>(smem + ns + AH_OFF + a_sts) = h;
            *reinterpret_cast<uint4*>(smem + ns + AL_OFF + a_sts) = l;
        }
        // prefetch A(c+2) and launch B(c+2)
        if (c + 2 < NCH) {
            const float* apn = ap + (size_t)(c + 2) * BK;
            ar0 = *reinterpret_cast<const float4*>(apn);
            ar1 = *reinterpret_cast<const float4*>(apn + 4);
            issue_stage_b(sb, (c + 2) % NSTG, c + 2, bwh, bwl, tid);
        }

        const uint32_t stg = sb + (uint32_t)(c % NSTG) * STAGE;
#pragma unroll
        for (int kk = 0; kk < 2; kk++) {
            const uint32_t ko = (uint32_t)(kk * 32);
            uint32_t ah[2][4], al[2][4];
#pragma unroll
            for (int mi = 0; mi < 2; mi++) {
                LDM4(ah[mi], stg + AH_OFF + a_ld + (uint32_t)(mi * 16 * LDAB) + ko);
                LDM4(al[mi], stg + AL_OFF + a_ld + (uint32_t)(mi * 16 * LDAB) + ko);
            }
#pragma unroll
            for (int g = 0; g < 2; g++) {
                uint32_t bh[4], bl[4];
                LDM4(bh, stg + BH_OFF + b_ld + (uint32_t)(g * 16 * LDAB) + ko);
                LDM4(bl, stg + BL_OFF + b_ld + (uint32_t)(g * 16 * LDAB) + ko);
#pragma unroll
                for (int mi = 0; mi < 2; mi++) {
                    MMA16816(c0[mi][g*2+0], ah[mi], bh[0], bh[1]);
                    MMA16816(c0[mi][g*2+1], ah[mi], bh[2], bh[3]);
                    MMA16816(c1[mi][g*2+0], ah[mi], bl[0], bl[1]);
                    MMA16816(c1[mi][g*2+1], ah[mi], bl[2], bl[3]);
                    MMA16816(c1[mi][g*2+0], al[mi], bh[0], bh[1]);
                    MMA16816(c1[mi][g*2+1], al[mi], bh[2], bh[3]);
                }
            }
        }
    }

    const int row0 = t0 + wm * 32 + (lane >> 2);
    const int col0 = e0 + wn * 32 + (lane & 3) * 2;
#pragma unroll
    for (int mi = 0; mi < 2; mi++) {
#pragma unroll
        for (int nj = 0; nj < 4; nj++) {
            float* p0 = g_logits + (size_t)(row0 + mi * 16) * NEXP + col0 + nj * 8;
            float* p1 = g_logits + (size_t)(row0 + mi * 16 + 8) * NEXP + col0 + nj * 8;
            *reinterpret_cast<float2*>(p0) =
                make_float2(fmaf(c1[mi][nj][0], LO_INV, c0[mi][nj][0]) * OUT_SCALE,
                            fmaf(c1[mi][nj][1], LO_INV, c0[mi][nj][1]) * OUT_SCALE);
            *reinterpret_cast<float2*>(p1) =
                make_float2(fmaf(c1[mi][nj][2], LO_INV, c0[mi][nj][2]) * OUT_SCALE,
                            fmaf(c1[mi][nj][3], LO_INV, c0[mi][nj][3]) * OUT_SCALE);
        }
    }
}

// ---------------------------------------------------------------------------
// Routing core (proven): one warp per token; pass1 flags low-margin tokens.
// ---------------------------------------------------------------------------
__device__ __forceinline__ void route_one(const float* __restrict__ lrow,
                                          const float* __restrict__ bias,
                                          int t, int lane, bool pass1,
                                          float* __restrict__ out_idx,
                                          float* __restrict__ out_w)
{
    float cand[NGRP];
    float gsum[NGRP];
#pragma unroll
    for (int j = 0; j < NGRP; j++) {
        const int e = j * 32 + lane;
        const float lg = lrow[e];
        const float s = 1.0f / (1.0f + expf(-lg));
        const float cc = s + __ldg(&bias[e]);
        cand[j] = cc;
        float v = cc;
#pragma unroll
        for (int o = 16; o; o >>= 1) v += __shfl_xor_sync(0xffffffffu, v, o);
        gsum[j] = v;
    }

    unsigned gmask = 0;
    float g4 = 0.0f, g5 = 0.0f;
    {
        float gs[NGRP];
#pragma unroll
        for (int j = 0; j < NGRP; j++) gs[j] = gsum[j];
#pragma unroll
        for (int r = 0; r < KGRP + 1; r++) {
            int bi = 0; float bv = gs[0];
#pragma unroll
            for (int j = 1; j < NGRP; j++) if (gs[j] > bv) { bv = gs[j]; bi = j; }
            if (r < KGRP) { gmask |= 1u << bi; g4 = bv; }
            else          { g5 = bv; }
            gs[bi] = -INFINITY;
        }
    }
    const float margin_g = g4 - g5;

#pragma unroll
    for (int j = 0; j < NGRP; j++)
        if (!((gmask >> j) & 1u)) cand[j] = -INFINITY;

    float wsum = 0.0f, my_w = 0.0f;
    int   my_i = 0;
    float prev = 0.0f, margin_e = INFINITY;
#pragma unroll
    for (int r = 0; r < TOPK + 1; r++) {
        float bv = cand[0];
        int   be = lane;
#pragma unroll
        for (int j = 1; j < NGRP; j++) {
            const int e = j * 32 + lane;
            if (cand[j] > bv) { bv = cand[j]; be = e; }
        }
#pragma unroll
        for (int o = 16; o; o >>= 1) {
            const float ov = __shfl_xor_sync(0xffffffffu, bv, o);
            const int   oe = __shfl_xor_sync(0xffffffffu, be, o);
            if (ov > bv || (ov == bv && oe < be)) { bv = ov; be = oe; }
        }
        if (r > 0) margin_e = fminf(margin_e, prev - bv);
        prev = bv;
        if (r < TOPK) {
            const int jw = be >> 5;
            const int lw = be & 31;
            if (lane == lw) {
#pragma unroll
                for (int j = 0; j < NGRP; j++) if (j == jw) cand[j] = -INFINITY;
            }
            const float wgt = bv - __ldg(&bias[be]);
            wsum += wgt;
            if (lane == r) { my_w = wgt; my_i = be; }
        }
    }

    if (lane < TOPK) {
        out_idx[t * TOPK + lane] = (float)my_i;
        out_w[t * TOPK + lane]   = my_w / (wsum + 1e-20f) * 2.5f;
    }
    if (pass1 && lane == 0 && (margin_e < D_EXPERT || margin_g < D_GROUP)) {
        int idx = atomicAdd(&g_fix_count, 1);
        if (idx < CAP) g_fix_list[idx] = t;
    }
}

__global__ void route_kernel(const float* __restrict__ bias,
                             float* __restrict__ out_idx,
                             float* __restrict__ out_w)
{
    const int warp = threadIdx.x >> 5;
    const int lane = threadIdx.x & 31;
    const int t = blockIdx.x * 8 + warp;
    if (t >= NTOK) return;
    route_one(g_logits + (size_t)t * NEXP, bias, t, lane, true, out_idx, out_w);
}

// ---------------------------------------------------------------------------
// Fixup GEMM (proven R10): unit = (token, 8-expert slice), warp per expert.
// ---------------------------------------------------------------------------
__global__ void fix_gemm_kernel(const float* __restrict__ x,
                                const float* __restrict__ w)
{
    const int cnt = min(g_fix_count, CAP);
    const int units = cnt * 32;
    const int warp = threadIdx.x >> 5;
    const int lane = threadIdx.x & 31;
    for (int u = blockIdx.x; u < units; u += gridDim.x) {
        const int i = u >> 5;
        const int e = (u & 31) * 8 + warp;
        const float4* xr = reinterpret_cast<const float4*>(x + (size_t)g_fix_list[i] * HID);
        const float4* wr = reinterpret_cast<const float4*>(w + (size_t)e * HID);
        float4 s0 = make_float4(0.f,0.f,0.f,0.f), s1 = s0, s2 = s0, s3 = s0;
#pragma unroll
        for (int j = 0; j < 14; j++) {
            const int b = j * 128 + lane;
            const float4 a0 = xr[b],      w0 = wr[b];
            const float4 a1 = xr[b + 32], w1 = wr[b + 32];
            const float4 a2 = xr[b + 64], w2 = wr[b + 64];
            const float4 a3 = xr[b + 96], w3 = wr[b + 96];
            s0.x = fmaf(a0.x, w0.x, s0.x); s0.y = fmaf(a0.y, w0.y, s0.y);
            s0.z = fmaf(a0.z, w0.z, s0.z); s0.w = fmaf(a0.w, w0.w, s0.w);
            s1.x = fmaf(a1.x, w1.x, s1.x); s1.y = fmaf(a1.y, w1.y, s1.y);
            s1.z = fmaf(a1.z, w1.z, s1.z); s1.w = fmaf(a1.w, w1.w, s1.w);
            s2.x = fmaf(a2.x, w2.x, s2.x); s2.y = fmaf(a2.y, w2.y, s2.y);
            s2.z = fmaf(a2.z, w2.z, s2.z); s2.w = fmaf(a2.w, w2.w, s2.w);
            s3.x = fmaf(a3.x, w3.x, s3.x); s3.y = fmaf(a3.y, w3.y, s3.y);
            s3.z = fmaf(a3.z, w3.z, s3.z); s3.w = fmaf(a3.w, w3.w, s3.w);
        }
        float v = (((s0.x + s0.y) + (s0.z + s0.w)) + ((s1.x + s1.y) + (s1.z + s1.w)))
                + (((s2.x + s2.y) + (s2.z + s2.w)) + ((s3.x + s3.y) + (s3.z + s3.w)));
#pragma unroll
        for (int o = 16; o; o >>= 1) v += __shfl_xor_sync(0xffffffffu, v, o);
        if (lane == 0) g_fix_logits[(size_t)i * NEXP + e] = v;
    }
}

__global__ void fix_route_kernel(const float* __restrict__ bias,
                                 float* __restrict__ out_idx,
                                 float* __restrict__ out_w)
{
    const int warp = threadIdx.x >> 5;
    const int lane = threadIdx.x & 31;
    const int i = blockIdx.x * 8 + warp;
    const int cnt = min(g_fix_count, CAP);
    if (i >= cnt) return;
    route_one(g_fix_logits + (size_t)i * NEXP, bias, g_fix_list[i], lane, false,
              out_idx, out_w);
}

// ---------------------------------------------------------------------------
extern "C" void kernel_launch(void* const* d_in, const int* in_sizes, int n_in,
                              void* d_out, int out_size)
{
    const float* x    = (const float*)d_in[0];
    const float* w    = (const float*)d_in[1];
    const float* bias = (const float*)d_in[2];
    float* out = (float*)d_out;
    float* out_w = out + (size_t)NTOK * TOPK;

    cudaFuncSetAttribute(gemm_hmma_kernel, cudaFuncAttributeMaxDynamicSharedMemorySize, SMEM_BYTES);

    convert_w_kernel<<<NEXP * HID / 8 / 256, 256>>>(w);
    gemm_hmma_kernel<<<dim3(128, 2), 256, SMEM_BYTES>>>(x);
    route_kernel<<<NTOK / 8, 256>>>(bias, out, out_w);
    fix_gemm_kernel<<<2048, 256>>>(x, w);
    fix_route_kernel<<<CAP / 8, 256>>>(bias, out, out_w);
}

// round 15
// speedup vs baseline: 1.3501x; 1.0477x over previous
#include <cuda_runtime.h>
#include <cuda_fp16.h>
#include <cstdint>
#include <math.h>

#define HID   7168
#define NEXP  256
#define NTOK  8192
#define NGRP  8
#define EPG   32
#define KGRP  4
#define TOPK  8

#define BM    64
#define BN    128
#define BK    32
#define NCH   (HID / BK)   // 224

#define LO_SCALE 2048.0f
#define LO_INV   (1.0f / 2048.0f)
#define A_PRE    16.0f
#define B_PRE    1024.0f
#define OUT_SCALE (1.0f / (16.0f * 1024.0f))

#define D_EXPERT 4e-6f
#define D_GROUP  2.4e-5f
#define CAP 8192

// stage layout: rows padded to 80B (conflict-free ldmatrix)
#define LDAB   80
#define AH_OFF 0
#define AL_OFF 5120
#define BH_OFF 10240
#define BL_OFF 20480
#define STAGE  30720
#define NSTG   3
#define SMEM_BYTES (NSTG * STAGE)   // 92160

// combined convert kernel split point: w has 256*7168/8/256 = 896 blocks
#define WBLKS  (NEXP * HID / 8 / 256)

// Device scratch (allocation is forbidden)
__device__ float  g_logits[NTOK * NEXP];
__device__ __half g_wh[NEXP * HID];
__device__ __half g_wl[NEXP * HID];
__device__ __half g_xh[NTOK * HID];
__device__ __half g_xl[NTOK * HID];
__device__ int    g_fix_count;
__device__ int    g_fix_list[CAP];
__device__ float  g_fix_logits[CAP * NEXP];

// ---------------------------------------------------------------------------
__device__ __forceinline__ uint32_t smem_u32(const void* p) {
    uint32_t a;
    asm("{ .reg .u64 t; cvta.to.shared.u64 t, %1; cvt.u32.u64 %0, t; }" : "=r"(a) : "l"(p));
    return a;
}
#define CP_ASYNC16(dst, src) \
    asm volatile("cp.async.cg.shared.global [%0], [%1], 16;" :: "r"(dst), "l"(src))
#define CP_COMMIT() asm volatile("cp.async.commit_group;" ::: "memory")
#define CP_WAIT0()  asm volatile("cp.async.wait_group 0;" ::: "memory")
#define CP_WAIT1()  asm volatile("cp.async.wait_group 1;" ::: "memory")

#define LDM4(r, addr)                                                         \
    asm volatile("ldmatrix.sync.aligned.m8n8.x4.shared.b16 {%0,%1,%2,%3}, [%4];" \
        : "=r"((r)[0]), "=r"((r)[1]), "=r"((r)[2]), "=r"((r)[3]) : "r"(addr))

#define MMA16816(c, a, b0, b1)                                                \
    asm volatile("mma.sync.aligned.m16n8k16.row.col.f32.f16.f16.f32 "         \
        "{%0,%1,%2,%3}, {%4,%5,%6,%7}, {%8,%9}, {%0,%1,%2,%3};"               \
        : "+f"((c)[0]), "+f"((c)[1]), "+f"((c)[2]), "+f"((c)[3])              \
        : "r"((a)[0]), "r"((a)[1]), "r"((a)[2]), "r"((a)[3]), "r"(b0), "r"(b1))

__device__ __forceinline__ uint32_t pkh(__half a, __half b) {
    __half2 h = __halves2half2(a, b);
    return *reinterpret_cast<uint32_t*>(&h);
}

__device__ __forceinline__ void cvt8(float4 u, float4 v, float pre, uint4& h, uint4& l) {
    const float f[8] = { u.x * pre, u.y * pre, u.z * pre, u.w * pre,
                         v.x * pre, v.y * pre, v.z * pre, v.w * pre };
    __half hi[8], lo[8];
#pragma unroll
    for (int t = 0; t < 8; t++) {
        hi[t] = __float2half_rn(f[t]);
        lo[t] = __float2half_rn((f[t] - __half2float(hi[t])) * LO_SCALE);
    }
    h = make_uint4(pkh(hi[0],hi[1]), pkh(hi[2],hi[3]), pkh(hi[4],hi[5]), pkh(hi[6],hi[7]));
    l = make_uint4(pkh(lo[0],lo[1]), pkh(lo[2],lo[3]), pkh(lo[4],lo[5]), pkh(lo[6],lo[7]));
}

// ---------------------------------------------------------------------------
// combined convert: all blocks convert x; first WBLKS blocks also convert w
// ---------------------------------------------------------------------------
__global__ void convert_all_kernel(const float* __restrict__ x,
                                   const float* __restrict__ w)
{
    if (blockIdx.x == 0 && threadIdx.x == 0) g_fix_count = 0;

    size_t i = ((size_t)blockIdx.x * blockDim.x + threadIdx.x) * 8;
    {
        float4 u = *reinterpret_cast<const float4*>(x + i);
        float4 v = *reinterpret_cast<const float4*>(x + i + 4);
        uint4 h, l;
        cvt8(u, v, A_PRE, h, l);
        *reinterpret_cast<uint4*>(&g_xh[i]) = h;
        *reinterpret_cast<uint4*>(&g_xl[i]) = l;
    }
    if (blockIdx.x < WBLKS) {
        float4 u = *reinterpret_cast<const float4*>(w + i);
        float4 v = *reinterpret_cast<const float4*>(w + i + 4);
        uint4 h, l;
        cvt8(u, v, B_PRE, h, l);
        *reinterpret_cast<uint4*>(&g_wh[i]) = h;
        *reinterpret_cast<uint4*>(&g_wl[i]) = l;
    }
}

// ---------------------------------------------------------------------------
// stage loader (R10 exact): 6 x 16B cp.async per thread, one commit
// ---------------------------------------------------------------------------
__device__ __forceinline__ void issue_stage(uint32_t sb, int buf, int c,
    const __half* __restrict__ axh, const __half* __restrict__ axl,
    const __half* __restrict__ bwh, const __half* __restrict__ bwl, int tid)
{
    const uint32_t s = sb + (uint32_t)buf * STAGE;
    const int row = tid >> 2, ch = tid & 3;
    const size_t off = (size_t)row * HID + (size_t)c * BK + ch * 8;
    const uint32_t d = (uint32_t)(row * LDAB + ch * 16);
    CP_ASYNC16(s + AH_OFF + d, axh + off);
    CP_ASYNC16(s + AL_OFF + d, axl + off);
    CP_ASYNC16(s + BH_OFF + d, bwh + off);
    CP_ASYNC16(s + BL_OFF + d, bwl + off);
    CP_ASYNC16(s + BH_OFF + d + 64 * LDAB, bwh + off + (size_t)64 * HID);
    CP_ASYNC16(s + BL_OFF + d + 64 * LDAB, bwl + off + (size_t)64 * HID);
    CP_COMMIT();
}

// ---------------------------------------------------------------------------
// Pure LDSM/HMMA GEMM (R10 exact): 64x128 per CTA, 8 warps 32x32, grid (128,2),
// 2 CTAs/SM, 3-stage cp.async pipeline.
// ---------------------------------------------------------------------------
__global__ void __launch_bounds__(256, 2)
gemm_hmma_kernel()
{
    extern __shared__ char smem[];
    const uint32_t sb = smem_u32(smem);
    const int tid  = threadIdx.x;
    const int lane = tid & 31;
    const int warp = tid >> 5;
    const int wm   = warp & 1;
    const int wn   = warp >> 1;
    const int t0   = blockIdx.x * BM;
    const int e0   = blockIdx.y * BN;

    const __half* axh = g_xh + (size_t)t0 * HID;
    const __half* axl = g_xl + (size_t)t0 * HID;
    const __half* bwh = g_wh + (size_t)e0 * HID;
    const __half* bwl = g_wl + (size_t)e0 * HID;

    const uint32_t a_ld = (uint32_t)((wm * 32 + (lane & 15)) * LDAB) + (lane & 16);
    const uint32_t b_ld = (uint32_t)((wn * 32 + (lane & 7) + ((lane & 16) >> 1)) * LDAB)
                        + (uint32_t)((lane & 8) * 2);

    float c0[2][4][4], c1[2][4][4];
#pragma unroll
    for (int i = 0; i < 2; i++)
#pragma unroll
        for (int j = 0; j < 4; j++)
#pragma unroll
            for (int q = 0; q < 4; q++) { c0[i][j][q] = 0.0f; c1[i][j][q] = 0.0f; }

    issue_stage(sb, 0, 0, axh, axl, bwh, bwl, tid);
    issue_stage(sb, 1, 1, axh, axl, bwh, bwl, tid);

    for (int c = 0; c < NCH; c++) {
        if (c + 1 < NCH) CP_WAIT1(); else CP_WAIT0();
        __syncthreads();
        if (c + 2 < NCH) issue_stage(sb, (c + 2) % NSTG, c + 2, axh, axl, bwh, bwl, tid);

        const uint32_t stg = sb + (uint32_t)(c % NSTG) * STAGE;
#pragma unroll
        for (int kk = 0; kk < 2; kk++) {
            const uint32_t ko = (uint32_t)(kk * 32);
            uint32_t ah[2][4], al[2][4];
#pragma unroll
            for (int mi = 0; mi < 2; mi++) {
                LDM4(ah[mi], stg + AH_OFF + a_ld + (uint32_t)(mi * 16 * LDAB) + ko);
                LDM4(al[mi], stg + AL_OFF + a_ld + (uint32_t)(mi * 16 * LDAB) + ko);
            }
#pragma unroll
            for (int g = 0; g < 2; g++) {
                uint32_t bh[4], bl[4];
                LDM4(bh, stg + BH_OFF + b_ld + (uint32_t)(g * 16 * LDAB) + ko);
                LDM4(bl, stg + BL_OFF + b_ld + (uint32_t)(g * 16 * LDAB) + ko);
#pragma unroll
                for (int mi = 0; mi < 2; mi++) {
                    MMA16816(c0[mi][g*2+0], ah[mi], bh[0], bh[1]);
                    MMA16816(c0[mi][g*2+1], ah[mi], bh[2], bh[3]);
                    MMA16816(c1[mi][g*2+0], ah[mi], bl[0], bl[1]);
                    MMA16816(c1[mi][g*2+1], ah[mi], bl[2], bl[3]);
                    MMA16816(c1[mi][g*2+0], al[mi], bh[0], bh[1]);
                    MMA16816(c1[mi][g*2+1], al[mi], bh[2], bh[3]);
                }
            }
        }
    }

    const int row0 = t0 + wm * 32 + (lane >> 2);
    const int col0 = e0 + wn * 32 + (lane & 3) * 2;
#pragma unroll
    for (int mi = 0; mi < 2; mi++) {
#pragma unroll
        for (int nj = 0; nj < 4; nj++) {
            float* p0 = g_logits + (size_t)(row0 + mi * 16) * NEXP + col0 + nj * 8;
            float* p1 = g_logits + (size_t)(row0 + mi * 16 + 8) * NEXP + col0 + nj * 8;
            *reinterpret_cast<float2*>(p0) =
                make_float2(fmaf(c1[mi][nj][0], LO_INV, c0[mi][nj][0]) * OUT_SCALE,
                            fmaf(c1[mi][nj][1], LO_INV, c0[mi][nj][1]) * OUT_SCALE);
            *reinterpret_cast<float2*>(p1) =
                make_float2(fmaf(c1[mi][nj][2], LO_INV, c0[mi][nj][2]) * OUT_SCALE,
                            fmaf(c1[mi][nj][3], LO_INV, c0[mi][nj][3]) * OUT_SCALE);
        }
    }
}

// ---------------------------------------------------------------------------
// Routing core (proven): one warp per token; pass1 flags low-margin tokens.
// ---------------------------------------------------------------------------
__device__ __forceinline__ void route_one(const float* __restrict__ lrow,
                                          const float* __restrict__ bias,
                                          int t, int lane, bool pass1,
                                          float* __restrict__ out_idx,
                                          float* __restrict__ out_w)
{
    float cand[NGRP];
    float gsum[NGRP];
#pragma unroll
    for (int j = 0; j < NGRP; j++) {
        const int e = j * 32 + lane;
        const float lg = lrow[e];
        const float s = 1.0f / (1.0f + expf(-lg));
        const float cc = s + __ldg(&bias[e]);
        cand[j] = cc;
        float v = cc;
#pragma unroll
        for (int o = 16; o; o >>= 1) v += __shfl_xor_sync(0xffffffffu, v, o);
        gsum[j] = v;
    }

    unsigned gmask = 0;
    float g4 = 0.0f, g5 = 0.0f;
    {
        float gs[NGRP];
#pragma unroll
        for (int j = 0; j < NGRP; j++) gs[j] = gsum[j];
#pragma unroll
        for (int r = 0; r < KGRP + 1; r++) {
            int bi = 0; float bv = gs[0];
#pragma unroll
            for (int j = 1; j < NGRP; j++) if (gs[j] > bv) { bv = gs[j]; bi = j; }
            if (r < KGRP) { gmask |= 1u << bi; g4 = bv; }
            else          { g5 = bv; }
            gs[bi] = -INFINITY;
        }
    }
    const float margin_g = g4 - g5;

#pragma unroll
    for (int j = 0; j < NGRP; j++)
        if (!((gmask >> j) & 1u)) cand[j] = -INFINITY;

    float wsum = 0.0f, my_w = 0.0f;
    int   my_i = 0;
    float prev = 0.0f, margin_e = INFINITY;
#pragma unroll
    for (int r = 0; r < TOPK + 1; r++) {
        float bv = cand[0];
        int   be = lane;
#pragma unroll
        for (int j = 1; j < NGRP; j++) {
            const int e = j * 32 + lane;
            if (cand[j] > bv) { bv = cand[j]; be = e; }
        }
#pragma unroll
        for (int o = 16; o; o >>= 1) {
            const float ov = __shfl_xor_sync(0xffffffffu, bv, o);
            const int   oe = __shfl_xor_sync(0xffffffffu, be, o);
            if (ov > bv || (ov == bv && oe < be)) { bv = ov; be = oe; }
        }
        if (r > 0) margin_e = fminf(margin_e, prev - bv);
        prev = bv;
        if (r < TOPK) {
            const int jw = be >> 5;
            const int lw = be & 31;
            if (lane == lw) {
#pragma unroll
                for (int j = 0; j < NGRP; j++) if (j == jw) cand[j] = -INFINITY;
            }
            const float wgt = bv - __ldg(&bias[be]);
            wsum += wgt;
            if (lane == r) { my_w = wgt; my_i = be; }
        }
    }

    if (lane < TOPK) {
        out_idx[t * TOPK + lane] = (float)my_i;
        out_w[t * TOPK + lane]   = my_w / (wsum + 1e-20f) * 2.5f;
    }
    if (pass1 && lane == 0 && (margin_e < D_EXPERT || margin_g < D_GROUP)) {
        int idx = atomicAdd(&g_fix_count, 1);
        if (idx < CAP) g_fix_list[idx] = t;
    }
}

__global__ void route_kernel(const float* __restrict__ bias,
                             float* __restrict__ out_idx,
                             float* __restrict__ out_w)
{
    const int warp = threadIdx.x >> 5;
    const int lane = threadIdx.x & 31;
    const int t = blockIdx.x * 8 + warp;
    if (t >= NTOK) return;
    route_one(g_logits + (size_t)t * NEXP, bias, t, lane, true, out_idx, out_w);
}

// ---------------------------------------------------------------------------
// Fixup GEMM (proven R10 math): unit = (token, 8-expert slice), warp per expert.
// grid 4096 -> single strided round for typical fix counts.
// ---------------------------------------------------------------------------
__global__ void fix_gemm_kernel(const float* __restrict__ x,
                                const float* __restrict__ w)
{
    const int cnt = min(g_fix_count, CAP);
    const int units = cnt * 32;
    const int warp = threadIdx.x >> 5;
    const int lane = threadIdx.x & 31;
    for (int u = blockIdx.x; u < units; u += gridDim.x) {
        const int i = u >> 5;
        const int e = (u & 31) * 8 + warp;
        const float4* xr = reinterpret_cast<const float4*>(x + (size_t)g_fix_list[i] * HID);
        const float4* wr = reinterpret_cast<const float4*>(w + (size_t)e * HID);
        float4 s0 = make_float4(0.f,0.f,0.f,0.f), s1 = s0, s2 = s0, s3 = s0;
#pragma unroll
        for (int j = 0; j < 14; j++) {
            const int b = j * 128 + lane;
            const float4 a0 = xr[b],      w0 = wr[b];
            const float4 a1 = xr[b + 32], w1 = wr[b + 32];
            const float4 a2 = xr[b + 64], w2 = wr[b + 64];
            const float4 a3 = xr[b + 96], w3 = wr[b + 96];
            s0.x = fmaf(a0.x, w0.x, s0.x); s0.y = fmaf(a0.y, w0.y, s0.y);
            s0.z = fmaf(a0.z, w0.z, s0.z); s0.w = fmaf(a0.w, w0.w, s0.w);
            s1.x = fmaf(a1.x, w1.x, s1.x); s1.y = fmaf(a1.y, w1.y, s1.y);
            s1.z = fmaf(a1.z, w1.z, s1.z); s1.w = fmaf(a1.w, w1.w, s1.w);
            s2.x = fmaf(a2.x, w2.x, s2.x); s2.y = fmaf(a2.y, w2.y, s2.y);
            s2.z = fmaf(a2.z, w2.z, s2.z); s2.w = fmaf(a2.w, w2.w, s2.w);
            s3.x = fmaf(a3.x, w3.x, s3.x); s3.y = fmaf(a3.y, w3.y, s3.y);
            s3.z = fmaf(a3.z, w3.z, s3.z); s3.w = fmaf(a3.w, w3.w, s3.w);
        }
        float v = (((s0.x + s0.y) + (s0.z + s0.w)) + ((s1.x + s1.y) + (s1.z + s1.w)))
                + (((s2.x + s2.y) + (s2.z + s2.w)) + ((s3.x + s3.y) + (s3.z + s3.w)));
#pragma unroll
        for (int o = 16; o; o >>= 1) v += __shfl_xor_sync(0xffffffffu, v, o);
        if (lane == 0) g_fix_logits[(size_t)i * NEXP + e] = v;
    }
}

__global__ void fix_route_kernel(const float* __restrict__ bias,
                                 float* __restrict__ out_idx,
                                 float* __restrict__ out_w)
{
    const int warp = threadIdx.x >> 5;
    const int lane = threadIdx.x & 31;
    const int cnt = min(g_fix_count, CAP);
    for (int i = blockIdx.x * 8 + warp; i < cnt; i += gridDim.x * 8)
        route_one(g_fix_logits + (size_t)i * NEXP, bias, g_fix_list[i], lane, false,
                  out_idx, out_w);
}

// ---------------------------------------------------------------------------
extern "C" void kernel_launch(void* const* d_in, const int* in_sizes, int n_in,
                              void* d_out, int out_size)
{
    const float* x    = (const float*)d_in[0];
    const float* w    = (const float*)d_in[1];
    const float* bias = (const float*)d_in[2];
    float* out = (float*)d_out;
    float* out_w = out + (size_t)NTOK * TOPK;

    cudaFuncSetAttribute(gemm_hmma_kernel, cudaFuncAttributeMaxDynamicSharedMemorySize, SMEM_BYTES);

    convert_all_kernel<<<NTOK * HID / 8 / 256, 256>>>(x, w);
    gemm_hmma_kernel<<<dim3(128, 2), 256, SMEM_BYTES>>>();
    route_kernel<<<NTOK / 8, 256>>>(bias, out, out_w);
    fix_gemm_kernel<<<4096, 256>>>(x, w);
    fix_route_kernel<<<512, 256>>>(bias, out, out_w);
}

// round 16
// speedup vs baseline: 1.3555x; 1.0041x over previous
#include <cuda_runtime.h>
#include <cuda_fp16.h>
#include <cstdint>
#include <math.h>

#define HID   7168
#define NEXP  256
#define NTOK  8192
#define NGRP  8
#define EPG   32
#define KGRP  4
#define TOPK  8

#define BM    64
#define BN    128
#define BK    32
#define NCH   (HID / BK)   // 224

#define LO_SCALE 2048.0f
#define LO_INV   (1.0f / 2048.0f)
#define A_PRE    16.0f
#define B_PRE    1024.0f
#define OUT_SCALE (1.0f / (16.0f * 1024.0f))

#define D_EXPERT 4e-6f
#define D_GROUP  2.4e-5f
#define CAP 8192

// stage layout: rows padded to 80B (conflict-free ldmatrix)
#define LDAB   80
#define AH_OFF 0
#define AL_OFF 5120
#define BH_OFF 10240
#define BL_OFF 20480
#define STAGE  30720
#define NSTG   3
#define SMEM_BYTES (NSTG * STAGE)   // 92160

#define WBLKS  (NEXP * HID / 8 / 256)   // 896

// Device scratch (allocation is forbidden)
__device__ float  g_logits[NTOK * NEXP];
__device__ __half g_wh[NEXP * HID];
__device__ __half g_wl[NEXP * HID];
__device__ __half g_xh[NTOK * HID];
__device__ __half g_xl[NTOK * HID];
__device__ int    g_fix_count;
__device__ int    g_fix_list[CAP];
__device__ float  g_fix_logits[CAP * NEXP];

// ---------------------------------------------------------------------------
__device__ __forceinline__ uint32_t smem_u32(const void* p) {
    uint32_t a;
    asm("{ .reg .u64 t; cvta.to.shared.u64 t, %1; cvt.u32.u64 %0, t; }" : "=r"(a) : "l"(p));
    return a;
}
#define CP_ASYNC16(dst, src) \
    asm volatile("cp.async.cg.shared.global [%0], [%1], 16;" :: "r"(dst), "l"(src))
#define CP_COMMIT() asm volatile("cp.async.commit_group;" ::: "memory")
#define CP_WAIT0()  asm volatile("cp.async.wait_group 0;" ::: "memory")
#define CP_WAIT1()  asm volatile("cp.async.wait_group 1;" ::: "memory")

#define LDM4(r, addr)                                                         \
    asm volatile("ldmatrix.sync.aligned.m8n8.x4.shared.b16 {%0,%1,%2,%3}, [%4];" \
        : "=r"((r)[0]), "=r"((r)[1]), "=r"((r)[2]), "=r"((r)[3]) : "r"(addr))

#define MMA16816(c, a, b0, b1)                                                \
    asm volatile("mma.sync.aligned.m16n8k16.row.col.f32.f16.f16.f32 "         \
        "{%0,%1,%2,%3}, {%4,%5,%6,%7}, {%8,%9}, {%0,%1,%2,%3};"               \
        : "+f"((c)[0]), "+f"((c)[1]), "+f"((c)[2]), "+f"((c)[3])              \
        : "r"((a)[0]), "r"((a)[1]), "r"((a)[2]), "r"((a)[3]), "r"(b0), "r"(b1))

__device__ __forceinline__ uint32_t pkh(__half a, __half b) {
    __half2 h = __halves2half2(a, b);
    return *reinterpret_cast<uint32_t*>(&h);
}

__device__ __forceinline__ void cvt8(float4 u, float4 v, float pre, uint4& h, uint4& l) {
    const float f[8] = { u.x * pre, u.y * pre, u.z * pre, u.w * pre,
                         v.x * pre, v.y * pre, v.z * pre, v.w * pre };
    __half hi[8], lo[8];
#pragma unroll
    for (int t = 0; t < 8; t++) {
        hi[t] = __float2half_rn(f[t]);
        lo[t] = __float2half_rn((f[t] - __half2float(hi[t])) * LO_SCALE);
    }
    h = make_uint4(pkh(hi[0],hi[1]), pkh(hi[2],hi[3]), pkh(hi[4],hi[5]), pkh(hi[6],hi[7]));
    l = make_uint4(pkh(lo[0],lo[1]), pkh(lo[2],lo[3]), pkh(lo[4],lo[5]), pkh(lo[6],lo[7]));
}

// ---------------------------------------------------------------------------
// combined convert: all blocks convert x; first WBLKS blocks also convert w
// ---------------------------------------------------------------------------
__global__ void convert_all_kernel(const float* __restrict__ x,
                                   const float* __restrict__ w)
{
    if (blockIdx.x == 0 && threadIdx.x == 0) g_fix_count = 0;

    size_t i = ((size_t)blockIdx.x * blockDim.x + threadIdx.x) * 8;
    {
        float4 u = *reinterpret_cast<const float4*>(x + i);
        float4 v = *reinterpret_cast<const float4*>(x + i + 4);
        uint4 h, l;
        cvt8(u, v, A_PRE, h, l);
        *reinterpret_cast<uint4*>(&g_xh[i]) = h;
        *reinterpret_cast<uint4*>(&g_xl[i]) = l;
    }
    if (blockIdx.x < WBLKS) {
        float4 u = *reinterpret_cast<const float4*>(w + i);
        float4 v = *reinterpret_cast<const float4*>(w + i + 4);
        uint4 h, l;
        cvt8(u, v, B_PRE, h, l);
        *reinterpret_cast<uint4*>(&g_wh[i]) = h;
        *reinterpret_cast<uint4*>(&g_wl[i]) = l;
    }
}

// ---------------------------------------------------------------------------
// stage loader (R10 exact): 6 x 16B cp.async per thread, one commit
// ---------------------------------------------------------------------------
__device__ __forceinline__ void issue_stage(uint32_t sb, int buf, int c,
    const __half* __restrict__ axh, const __half* __restrict__ axl,
    const __half* __restrict__ bwh, const __half* __restrict__ bwl, int tid)
{
    const uint32_t s = sb + (uint32_t)buf * STAGE;
    const int row = tid >> 2, ch = tid & 3;
    const size_t off = (size_t)row * HID + (size_t)c * BK + ch * 8;
    const uint32_t d = (uint32_t)(row * LDAB + ch * 16);
    CP_ASYNC16(s + AH_OFF + d, axh + off);
    CP_ASYNC16(s + AL_OFF + d, axl + off);
    CP_ASYNC16(s + BH_OFF + d, bwh + off);
    CP_ASYNC16(s + BL_OFF + d, bwl + off);
    CP_ASYNC16(s + BH_OFF + d + 64 * LDAB, bwh + off + (size_t)64 * HID);
    CP_ASYNC16(s + BL_OFF + d + 64 * LDAB, bwl + off + (size_t)64 * HID);
    CP_COMMIT();
}

// ---------------------------------------------------------------------------
// Pure LDSM/HMMA GEMM (R10 exact): 64x128 per CTA, 8 warps 32x32, grid (128,2),
// 2 CTAs/SM, 3-stage cp.async pipeline.
// ---------------------------------------------------------------------------
__global__ void __launch_bounds__(256, 2)
gemm_hmma_kernel()
{
    extern __shared__ char smem[];
    const uint32_t sb = smem_u32(smem);
    const int tid  = threadIdx.x;
    const int lane = tid & 31;
    const int warp = tid >> 5;
    const int wm   = warp & 1;
    const int wn   = warp >> 1;
    const int t0   = blockIdx.x * BM;
    const int e0   = blockIdx.y * BN;

    const __half* axh = g_xh + (size_t)t0 * HID;
    const __half* axl = g_xl + (size_t)t0 * HID;
    const __half* bwh = g_wh + (size_t)e0 * HID;
    const __half* bwl = g_wl + (size_t)e0 * HID;

    const uint32_t a_ld = (uint32_t)((wm * 32 + (lane & 15)) * LDAB) + (lane & 16);
    const uint32_t b_ld = (uint32_t)((wn * 32 + (lane & 7) + ((lane & 16) >> 1)) * LDAB)
                        + (uint32_t)((lane & 8) * 2);

    float c0[2][4][4], c1[2][4][4];
#pragma unroll
    for (int i = 0; i < 2; i++)
#pragma unroll
        for (int j = 0; j < 4; j++)
#pragma unroll
            for (int q = 0; q < 4; q++) { c0[i][j][q] = 0.0f; c1[i][j][q] = 0.0f; }

    issue_stage(sb, 0, 0, axh, axl, bwh, bwl, tid);
    issue_stage(sb, 1, 1, axh, axl, bwh, bwl, tid);

    for (int c = 0; c < NCH; c++) {
        if (c + 1 < NCH) CP_WAIT1(); else CP_WAIT0();
        __syncthreads();
        if (c + 2 < NCH) issue_stage(sb, (c + 2) % NSTG, c + 2, axh, axl, bwh, bwl, tid);

        const uint32_t stg = sb + (uint32_t)(c % NSTG) * STAGE;
#pragma unroll
        for (int kk = 0; kk < 2; kk++) {
            const uint32_t ko = (uint32_t)(kk * 32);
            uint32_t ah[2][4], al[2][4];
#pragma unroll
            for (int mi = 0; mi < 2; mi++) {
                LDM4(ah[mi], stg + AH_OFF + a_ld + (uint32_t)(mi * 16 * LDAB) + ko);
                LDM4(al[mi], stg + AL_OFF + a_ld + (uint32_t)(mi * 16 * LDAB) + ko);
            }
#pragma unroll
            for (int g = 0; g < 2; g++) {
                uint32_t bh[4], bl[4];
                LDM4(bh, stg + BH_OFF + b_ld + (uint32_t)(g * 16 * LDAB) + ko);
                LDM4(bl, stg + BL_OFF + b_ld + (uint32_t)(g * 16 * LDAB) + ko);
#pragma unroll
                for (int mi = 0; mi < 2; mi++) {
                    MMA16816(c0[mi][g*2+0], ah[mi], bh[0], bh[1]);
                    MMA16816(c0[mi][g*2+1], ah[mi], bh[2], bh[3]);
                    MMA16816(c1[mi][g*2+0], ah[mi], bl[0], bl[1]);
                    MMA16816(c1[mi][g*2+1], ah[mi], bl[2], bl[3]);
                    MMA16816(c1[mi][g*2+0], al[mi], bh[0], bh[1]);
                    MMA16816(c1[mi][g*2+1], al[mi], bh[2], bh[3]);
                }
            }
        }
    }

    const int row0 = t0 + wm * 32 + (lane >> 2);
    const int col0 = e0 + wn * 32 + (lane & 3) * 2;
#pragma unroll
    for (int mi = 0; mi < 2; mi++) {
#pragma unroll
        for (int nj = 0; nj < 4; nj++) {
            float* p0 = g_logits + (size_t)(row0 + mi * 16) * NEXP + col0 + nj * 8;
            float* p1 = g_logits + (size_t)(row0 + mi * 16 + 8) * NEXP + col0 + nj * 8;
            *reinterpret_cast<float2*>(p0) =
                make_float2(fmaf(c1[mi][nj][0], LO_INV, c0[mi][nj][0]) * OUT_SCALE,
                            fmaf(c1[mi][nj][1], LO_INV, c0[mi][nj][1]) * OUT_SCALE);
            *reinterpret_cast<float2*>(p1) =
                make_float2(fmaf(c1[mi][nj][2], LO_INV, c0[mi][nj][2]) * OUT_SCALE,
                            fmaf(c1[mi][nj][3], LO_INV, c0[mi][nj][3]) * OUT_SCALE);
        }
    }
}

// ---------------------------------------------------------------------------
// Main route (FAST): redux-based argmax. Any token whose result could be
// perturbed by the pv=+1.0 rounding (<=6e-8) has margin ~0 << D_EXPERT and is
// flagged for the exact fixup path.
// ---------------------------------------------------------------------------
__global__ void route_kernel(const float* __restrict__ bias,
                             float* __restrict__ out_idx,
                             float* __restrict__ out_w)
{
    const int warp = threadIdx.x >> 5;
    const int lane = threadIdx.x & 31;
    const int t = blockIdx.x * 8 + warp;
    if (t >= NTOK) return;

    const float* lrow = g_logits + (size_t)t * NEXP;

    float cand[NGRP];
    float gsum[NGRP];
#pragma unroll
    for (int j = 0; j < NGRP; j++) {
        const int e = j * 32 + lane;
        const float lg = lrow[e];
        const float s = 1.0f / (1.0f + expf(-lg));
        const float cc = s + __ldg(&bias[e]);
        cand[j] = cc;
        float v = cc;
#pragma unroll
        for (int o = 16; o; o >>= 1) v += __shfl_xor_sync(0xffffffffu, v, o);
        gsum[j] = v;
    }

    unsigned gmask = 0;
    float g4 = 0.0f, g5 = 0.0f;
    {
        float gs[NGRP];
#pragma unroll
        for (int j = 0; j < NGRP; j++) gs[j] = gsum[j];
#pragma unroll
        for (int r = 0; r < KGRP + 1; r++) {
            int bi = 0; float bv = gs[0];
#pragma unroll
            for (int j = 1; j < NGRP; j++) if (gs[j] > bv) { bv = gs[j]; bi = j; }
            if (r < KGRP) { gmask |= 1u << bi; g4 = bv; }
            else          { g5 = bv; }
            gs[bi] = -INFINITY;
        }
    }
    const float margin_g = g4 - g5;

    // pv bits: positive monotone encoding; masked = 0
    unsigned pb[NGRP];
#pragma unroll
    for (int j = 0; j < NGRP; j++)
        pb[j] = ((gmask >> j) & 1u) ? __float_as_uint(cand[j] + 1.0f) : 0u;

    float wsum = 0.0f, my_w = 0.0f;
    int   my_i = 0;
    float prevf = 0.0f, margin_e = INFINITY;
#pragma unroll
    for (int r = 0; r < TOPK + 1; r++) {
        unsigned best = pb[0]; int bj = 0;
#pragma unroll
        for (int j = 1; j < NGRP; j++) if (pb[j] > best) { best = pb[j]; bj = j; }
        const unsigned m = __reduce_max_sync(0xffffffffu, best);
        const unsigned cte = (best == m) ? (unsigned)(bj * 32 + lane) : 0xFFFFFFFFu;
        const unsigned we = __reduce_min_sync(0xffffffffu, cte);
        const float bvf = __uint_as_float(m) - 1.0f;
        if (r > 0) margin_e = fminf(margin_e, prevf - bvf);
        prevf = bvf;
        if (r < TOPK) {
            if (lane == (int)(we & 31u)) pb[we >> 5] = 0u;
            const float wgt = bvf - __ldg(&bias[we]);
            wsum += wgt;
            if (lane == r) { my_w = wgt; my_i = (int)we; }
        }
    }

    if (lane < TOPK) {
        out_idx[t * TOPK + lane] = (float)my_i;
        out_w[t * TOPK + lane]   = my_w / (wsum + 1e-20f) * 2.5f;
    }
    if (lane == 0 && (margin_e < D_EXPERT || margin_g < D_GROUP)) {
        int idx = atomicAdd(&g_fix_count, 1);
        if (idx < CAP) g_fix_list[idx] = t;
    }
}

// ---------------------------------------------------------------------------
// Exact routing core for the fixup path (unchanged R7 logic).
// ---------------------------------------------------------------------------
__device__ __forceinline__ void route_one_exact(const float* __restrict__ lrow,
                                                const float* __restrict__ bias,
                                                int t, int lane,
                                                float* __restrict__ out_idx,
                                                float* __restrict__ out_w)
{
    float cand[NGRP];
    float gsum[NGRP];
#pragma unroll
    for (int j = 0; j < NGRP; j++) {
        const int e = j * 32 + lane;
        const float lg = lrow[e];
        const float s = 1.0f / (1.0f + expf(-lg));
        const float cc = s + __ldg(&bias[e]);
        cand[j] = cc;
        float v = cc;
#pragma unroll
        for (int o = 16; o; o >>= 1) v += __shfl_xor_sync(0xffffffffu, v, o);
        gsum[j] = v;
    }

    unsigned gmask = 0;
    {
        float gs[NGRP];
#pragma unroll
        for (int j = 0; j < NGRP; j++) gs[j] = gsum[j];
#pragma unroll
        for (int r = 0; r < KGRP; r++) {
            int bi = 0; float bv = gs[0];
#pragma unroll
            for (int j = 1; j < NGRP; j++) if (gs[j] > bv) { bv = gs[j]; bi = j; }
            gmask |= 1u << bi;
            gs[bi] = -INFINITY;
        }
    }

#pragma unroll
    for (int j = 0; j < NGRP; j++)
        if (!((gmask >> j) & 1u)) cand[j] = -INFINITY;

    float wsum = 0.0f, my_w = 0.0f;
    int   my_i = 0;
#pragma unroll
    for (int r = 0; r < TOPK; r++) {
        float bv = cand[0];
        int   be = lane;
#pragma unroll
        for (int j = 1; j < NGRP; j++) {
            const int e = j * 32 + lane;
            if (cand[j] > bv) { bv = cand[j]; be = e; }
        }
#pragma unroll
        for (int o = 16; o; o >>= 1) {
            const float ov = __shfl_xor_sync(0xffffffffu, bv, o);
            const int   oe = __shfl_xor_sync(0xffffffffu, be, o);
            if (ov > bv || (ov == bv && oe < be)) { bv = ov; be = oe; }
        }
        const int jw = be >> 5;
        const int lw = be & 31;
        if (lane == lw) {
#pragma unroll
            for (int j = 0; j < NGRP; j++) if (j == jw) cand[j] = -INFINITY;
        }
        const float wgt = bv - __ldg(&bias[be]);
        wsum += wgt;
        if (lane == r) { my_w = wgt; my_i = be; }
    }

    if (lane < TOPK) {
        out_idx[t * TOPK + lane] = (float)my_i;
        out_w[t * TOPK + lane]   = my_w / (wsum + 1e-20f) * 2.5f;
    }
}

// ---------------------------------------------------------------------------
// Fixup GEMM (proven): unit = (token, 8-expert slice), warp per expert.
// ---------------------------------------------------------------------------
__global__ void fix_gemm_kernel(const float* __restrict__ x,
                                const float* __restrict__ w)
{
    const int cnt = min(g_fix_count, CAP);
    const int units = cnt * 32;
    const int warp = threadIdx.x >> 5;
    const int lane = threadIdx.x & 31;
    for (int u = blockIdx.x; u < units; u += gridDim.x) {
        const int i = u >> 5;
        const int e = (u & 31) * 8 + warp;
        const float4* xr = reinterpret_cast<const float4*>(x + (size_t)g_fix_list[i] * HID);
        const float4* wr = reinterpret_cast<const float4*>(w + (size_t)e * HID);
        float4 s0 = make_float4(0.f,0.f,0.f,0.f), s1 = s0, s2 = s0, s3 = s0;
#pragma unroll
        for (int j = 0; j < 14; j++) {
            const int b = j * 128 + lane;
            const float4 a0 = xr[b],      w0 = wr[b];
            const float4 a1 = xr[b + 32], w1 = wr[b + 32];
            const float4 a2 = xr[b + 64], w2 = wr[b + 64];
            const float4 a3 = xr[b + 96], w3 = wr[b + 96];
            s0.x = fmaf(a0.x, w0.x, s0.x); s0.y = fmaf(a0.y, w0.y, s0.y);
            s0.z = fmaf(a0.z, w0.z, s0.z); s0.w = fmaf(a0.w, w0.w, s0.w);
            s1.x = fmaf(a1.x, w1.x, s1.x); s1.y = fmaf(a1.y, w1.y, s1.y);
            s1.z = fmaf(a1.z, w1.z, s1.z); s1.w = fmaf(a1.w, w1.w, s1.w);
            s2.x = fmaf(a2.x, w2.x, s2.x); s2.y = fmaf(a2.y, w2.y, s2.y);
            s2.z = fmaf(a2.z, w2.z, s2.z); s2.w = fmaf(a2.w, w2.w, s2.w);
            s3.x = fmaf(a3.x, w3.x, s3.x); s3.y = fmaf(a3.y, w3.y, s3.y);
            s3.z = fmaf(a3.z, w3.z, s3.z); s3.w = fmaf(a3.w, w3.w, s3.w);
        }
        float v = (((s0.x + s0.y) + (s0.z + s0.w)) + ((s1.x + s1.y) + (s1.z + s1.w)))
                + (((s2.x + s2.y) + (s2.z + s2.w)) + ((s3.x + s3.y) + (s3.z + s3.w)));
#pragma unroll
        for (int o = 16; o; o >>= 1) v += __shfl_xor_sync(0xffffffffu, v, o);
        if (lane == 0) g_fix_logits[(size_t)i * NEXP + e] = v;
    }
}

__global__ void fix_route_kernel(const float* __restrict__ bias,
                                 float* __restrict__ out_idx,
                                 float* __restrict__ out_w)
{
    const int warp = threadIdx.x >> 5;
    const int lane = threadIdx.x & 31;
    const int cnt = min(g_fix_count, CAP);
    for (int i = blockIdx.x * 8 + warp; i < cnt; i += gridDim.x * 8)
        route_one_exact(g_fix_logits + (size_t)i * NEXP, bias, g_fix_list[i], lane,
                        out_idx, out_w);
}

// ---------------------------------------------------------------------------
extern "C" void kernel_launch(void* const* d_in, const int* in_sizes, int n_in,
                              void* d_out, int out_size)
{
    const float* x    = (const float*)d_in[0];
    const float* w    = (const float*)d_in[1];
    const float* bias = (const float*)d_in[2];
    float* out = (float*)d_out;
    float* out_w = out + (size_t)NTOK * TOPK;

    cudaFuncSetAttribute(gemm_hmma_kernel, cudaFuncAttributeMaxDynamicSharedMemorySize, SMEM_BYTES);

    convert_all_kernel<<<NTOK * HID / 8 / 256, 256>>>(x, w);
    gemm_hmma_kernel<<<dim3(128, 2), 256, SMEM_BYTES>>>();
    route_kernel<<<NTOK / 8, 256>>>(bias, out, out_w);
    fix_gemm_kernel<<<4096, 256>>>(x, w);
    fix_route_kernel<<<128, 256>>>(bias, out, out_w);
}